// round 16
// baseline (speedup 1.0000x reference)
#include <cuda_runtime.h>
#include <cuda_fp16.h>
#include <math.h>
#include <stdint.h>

#define DIM 768
#define HEADS 12
#define HEAD_DIM 64
#define BATCH 64
#define SEQ 196
#define MTOT (BATCH * SEQ)      // 12544
#define SCALE 0.125f
#define QKVS 2304               // combined q|k|v row stride

// ---------------- scratch (all fp16 intermediates) ----------------
__device__ __half gx_h[(size_t)MTOT * DIM];
__device__ __half gqkv_h[(size_t)MTOT * QKVS];     // q|k|v
__device__ __half go_h[(size_t)MTOT * DIM];
__device__ __half gqkvw_h[QKVS * DIM];             // qk_w rows 0..1535, v_w rows 1536..2303
__device__ __half gpw_h[DIM * DIM];
__device__ float g_pos[HEADS * 729];

// ---------------- helpers ----------------
__device__ __forceinline__ uint32_t packh2(float x, float y) {
    __half2 h = __floats2half2_rn(x, y);
    return *(uint32_t*)&h;
}

__device__ __forceinline__ void mma_f16(float* c, const uint32_t* a, uint32_t b0, uint32_t b1) {
    asm volatile(
        "mma.sync.aligned.m16n8k16.row.col.f32.f16.f16.f32 "
        "{%0,%1,%2,%3}, {%4,%5,%6,%7}, {%8,%9}, {%0,%1,%2,%3};\n"
        : "+f"(c[0]), "+f"(c[1]), "+f"(c[2]), "+f"(c[3])
        : "r"(a[0]), "r"(a[1]), "r"(a[2]), "r"(a[3]), "r"(b0), "r"(b1));
}

__device__ __forceinline__ uint32_t smem_u32(const void* p) {
    uint32_t a;
    asm("{ .reg .u64 t; cvta.to.shared.u64 t, %1; cvt.u32.u64 %0, t; }" : "=r"(a) : "l"(p));
    return a;
}

#define LDSM_X4(r0, r1, r2, r3, addr) \
    asm volatile("ldmatrix.sync.aligned.m8n8.x4.shared.b16 {%0,%1,%2,%3}, [%4];" \
                 : "=r"(r0), "=r"(r1), "=r"(r2), "=r"(r3) : "r"(addr))

#define LDSM_X4_T(r0, r1, r2, r3, addr) \
    asm volatile("ldmatrix.sync.aligned.m8n8.x4.trans.shared.b16 {%0,%1,%2,%3}, [%4];" \
                 : "=r"(r0), "=r"(r1), "=r"(r2), "=r"(r3) : "r"(addr))

#define CP_ASYNC16(smaddr, gptr) \
    asm volatile("cp.async.cg.shared.global [%0], [%1], 16;" :: "r"(smaddr), "l"(gptr) : "memory")
#define CP_COMMIT() asm volatile("cp.async.commit_group;" ::: "memory")
#define CP_WAIT(n)  asm volatile("cp.async.wait_group %0;" :: "n"(n) : "memory")

// ---------------- merged fp32 -> fp16 convert (x, qk_w, v_w, proj_w) ----------------
#define NX (MTOT * DIM)
#define NQK (2 * DIM * DIM)
#define NV (DIM * DIM)
#define NCONV_TOT (NX + NQK + NV + NV)

__global__ void conv_all(const float* __restrict__ x, const float* __restrict__ qk_w,
                         const float* __restrict__ v_w, const float* __restrict__ proj_w,
                         __half* __restrict__ xh, __half* __restrict__ qkvwh,
                         __half* __restrict__ pwh)
{
    size_t i = ((size_t)blockIdx.x * 256 + threadIdx.x) * 4;
    if (i >= NCONV_TOT) return;
    const float* src;
    __half* dst;
    size_t off;
    if (i < NX) { src = x; dst = xh; off = i; }
    else if (i < NX + NQK) { src = qk_w; dst = qkvwh; off = i - NX; }
    else if (i < NX + NQK + NV) { src = v_w; dst = qkvwh + NQK; off = i - NX - NQK; }
    else { src = proj_w; dst = pwh; off = i - NX - NQK - NV; }
    float4 v = *(const float4*)&src[off];
    uint2 p;
    p.x = packh2(v.x, v.y);
    p.y = packh2(v.z, v.w);
    *(uint2*)&dst[off] = p;
}

// ---------------- pos table ----------------
__global__ void pos_kernel(const float* __restrict__ w1,
                           const float* __restrict__ b1,
                           const float* __restrict__ w2,
                           const float* __restrict__ b2,
                           float* __restrict__ out)
{
    int c = blockIdx.x;
    float dx = (float)(c % 27 - 13);
    float dy = (float)(c / 27 - 13);
    int h = threadIdx.x >> 5;
    int lane = threadIdx.x & 31;
    float sum = 0.f;
#pragma unroll
    for (int mm = lane; mm < HEAD_DIM; mm += 32) {
        int g = h * HEAD_DIM + mm;
        float t = fmaf(dx, w1[g * 2 + 0], fmaf(dy, w1[g * 2 + 1], b1[g]));
        t = fmaxf(t, 0.f);
        sum += t * w2[g];
    }
#pragma unroll
    for (int o = 16; o > 0; o >>= 1) sum += __shfl_xor_sync(0xffffffffu, sum, o);
    if (lane == 0) out[h * 729 + c] = sum + b2[h];
}

// ---------------- pure-fp16 GEMM: BM=256, BN=128, warp tile 64x64 ----------------
// 256 threads, warp grid 4x2 (wm = w>>1, wn = w&1). 3-stage cp.async ring,
// always-commit tail. smem rows: A 0..255, B 256..383, stride 36 words.
#define HSTRW 36
#define HROWS 384
#define HBUF_W (HROWS * HSTRW)          // words per stage
#define HSTAGES 3
#define HSM_BYTES (HSTAGES * HBUF_W * 4)  // 165888

template <bool OUT_FLOAT>
__global__ __launch_bounds__(256, 1)
void gemm_h(const __half* __restrict__ A, const __half* __restrict__ B,
            const float* __restrict__ bias, void* __restrict__ Cout,
            int M, int N, int K)
{
    extern __shared__ uint32_t sm[];

    int tid = threadIdx.x;
    int lane = tid & 31;
    int w = tid >> 5;
    int wm = w >> 1;            // 0..3 (64-row slice)
    int wn = w & 1;             // 0..1 (64-col slice)
    int lq = lane >> 2;         // 0..7
    int lr = lane & 3;          // 0..3
    int m0 = blockIdx.y * 256;
    int n0 = blockIdx.x * 128;

    uint32_t rowSelA = (lane & 7) + ((lane >> 3) & 1) * 8;
    uint32_t colSelA = (lane >> 4) * 4;
    uint32_t rowSelB = (lane & 7) + (lane >> 4) * 8;
    uint32_t colSelB = ((lane >> 3) & 1) * 4;

    float acc[4][8][4];
#pragma unroll
    for (int i = 0; i < 4; i++)
#pragma unroll
        for (int j = 0; j < 8; j++)
#pragma unroll
            for (int t = 0; t < 4; t++) acc[i][j][t] = 0.f;

    uint32_t smb = smem_u32(sm);
    int NT_K = K / 64;

    // loader: 3072 16B chunks per stage; rows 0..255 = A, 256..383 = B
    auto issue = [&](int buf, int k0) {
#pragma unroll
        for (int i = 0; i < 12; i++) {
            int c = tid + i * 256;
            int row = c >> 3, c8 = c & 7;
            uint32_t dst = smb + (buf * HBUF_W + row * HSTRW + c8 * 4) * 4;
            const __half* g = (row < 256)
                ? A + (size_t)(m0 + row) * K + k0 + c8 * 8
                : B + (size_t)(n0 + row - 256) * K + k0 + c8 * 8;
            CP_ASYNC16(dst, g);
        }
        CP_COMMIT();
    };

    issue(0, 0);
    issue(1, 64);

    int buf = 0;
    for (int kt = 0; kt < NT_K; kt++) {
        CP_WAIT(1);                 // tile kt landed (kt+1 may still fly)
        __syncthreads();

        if (kt + 2 < NT_K) issue((kt + 2) % HSTAGES, (kt + 2) * 64);
        else CP_COMMIT();           // empty group keeps wait(1) invariant at tail

        uint32_t abase = smb + (buf * HBUF_W) * 4;
        uint32_t aAddr = abase + ((wm * 64 + rowSelA) * HSTRW + colSelA) * 4;
        uint32_t bAddr = abase + ((256 + wn * 64 + rowSelB) * HSTRW + colSelB) * 4;

#pragma unroll
        for (int ks = 0; ks < 4; ks++) {
            int kb = ks * 8;
            uint32_t af[4][4], bf[8][2];
#pragma unroll
            for (int i = 0; i < 4; i++)
                LDSM_X4(af[i][0], af[i][1], af[i][2], af[i][3],
                        aAddr + (i * 16 * HSTRW + kb) * 4);
#pragma unroll
            for (int jp = 0; jp < 4; jp++)
                LDSM_X4(bf[2 * jp][0], bf[2 * jp][1], bf[2 * jp + 1][0], bf[2 * jp + 1][1],
                        bAddr + (jp * 16 * HSTRW + kb) * 4);
#pragma unroll
            for (int i = 0; i < 4; i++)
#pragma unroll
                for (int j = 0; j < 8; j++)
                    mma_f16(acc[i][j], af[i], bf[j][0], bf[j][1]);
        }
        buf = (buf + 1) % HSTAGES;
    }

#pragma unroll
    for (int i = 0; i < 4; i++) {
#pragma unroll
        for (int j = 0; j < 8; j++) {
            int row = m0 + wm * 64 + i * 16 + lq;
            int col = n0 + wn * 64 + j * 8 + lr * 2;
            float b0 = bias ? bias[col] : 0.f;
            float b1 = bias ? bias[col + 1] : 0.f;
            if (OUT_FLOAT) {
                float* C = (float*)Cout;
                *(float2*)&C[(size_t)row * N + col] =
                    make_float2(acc[i][j][0] + b0, acc[i][j][1] + b1);
                *(float2*)&C[(size_t)(row + 8) * N + col] =
                    make_float2(acc[i][j][2] + b0, acc[i][j][3] + b1);
            } else {
                __half* C = (__half*)Cout;
                *(uint32_t*)&C[(size_t)row * N + col] = packh2(acc[i][j][0] + b0, acc[i][j][1] + b1);
                *(uint32_t*)&C[(size_t)(row + 8) * N + col] = packh2(acc[i][j][2] + b0, acc[i][j][3] + b1);
            }
        }
    }
}

// ---------------- FP16 MMA attention: V untransposed + ldmatrix.trans ----------
// smem: K [224][72 halves], V [224][72 halves] (rows j, cols d), pos[729], colc[224]
#define KSH_W 36            // words per K row
#define VSH_W 36            // words per V row
#define NPAD 224
#define CNT 14
#define ATTN_SM_WORDS (NPAD * KSH_W + NPAD * VSH_W + 729 + NPAD)

__global__ __launch_bounds__(256, 2)
void attn_mma(const __half* __restrict__ qkv,
              const float* __restrict__ pos,
              __half* __restrict__ og)
{
    extern __shared__ uint32_t smu[];
    uint32_t* Kw   = smu;                        // [224][36] words
    uint32_t* Vw   = Kw + NPAD * KSH_W;          // [224][36] words (V rows j)
    float*    posh = (float*)(Vw + NPAD * VSH_W);
    int*      colc = (int*)(posh + 729);

    int bh = blockIdx.x;
    int b = bh / HEADS;
    int h = bh % HEADS;
    int tid = threadIdx.x;
    int w = tid >> 5;
    int lane = tid & 31;
    int lq = lane >> 2;
    int lr = lane & 3;

    // K (non-trans) selectors
    uint32_t rowSelB = (lane & 7) + (lane >> 4) * 8;
    uint32_t colSelB = ((lane >> 3) & 1) * 4;
    // V (trans) selectors: rows = j (m dim of stored V), cols = d
    uint32_t rowSelV = (lane & 7) + ((lane >> 3) & 1) * 8;  // j offset
    uint32_t colSelV = (lane >> 4) * 8;                     // d offset (halves)
    uint32_t kAddrBase, vAddrBase;
    {
        uint32_t kb = smem_u32(Kw), vb = smem_u32(Vw);
        kAddrBase = kb + (rowSelB * KSH_W + colSelB) * 4;
        vAddrBase = vb + rowSelV * VSH_W * 4 + colSelV * 2;
    }

    // zero pads: K and V rows 196..223
    for (int idx = tid; idx < 28 * KSH_W; idx += 256) {
        Kw[196 * KSH_W + idx] = 0;
        Vw[196 * VSH_W + idx] = 0;
    }

    // stage K and V rows 0..195 (pure uint4 copies)
    for (int idx = tid; idx < SEQ * 8; idx += 256) {
        int j = idx >> 3, c8 = idx & 7;
        *(uint4*)&Kw[j * KSH_W + c8 * 4] =
            *(const uint4*)&qkv[(size_t)(b * SEQ + j) * QKVS + DIM + h * HEAD_DIM + c8 * 8];
        *(uint4*)&Vw[j * VSH_W + c8 * 4] =
            *(const uint4*)&qkv[(size_t)(b * SEQ + j) * QKVS + 2 * DIM + h * HEAD_DIM + c8 * 8];
    }
    for (int c = tid; c < 729; c += 256) posh[c] = pos[h * 729 + c];
    for (int c = tid; c < NPAD; c += 256) {
        int cc = c > 195 ? 195 : c;
        colc[c] = (cc / 14) * 27 + (cc % 14);
    }
    __syncthreads();

    for (int mt = w; mt < 13; mt += 8) {
        int m0 = mt * 16;
        int r1 = m0 + lq, r2 = r1 + 8;
        int r1c = r1 > 195 ? 195 : r1;
        int r2c = r2 > 195 ? 195 : r2;
        const __half* q1 = &qkv[(size_t)(b * SEQ + r1c) * QKVS + h * HEAD_DIM];
        const __half* q2 = &qkv[(size_t)(b * SEQ + r2c) * QKVS + h * HEAD_DIM];

        uint32_t af[4][4];
#pragma unroll
        for (int ks = 0; ks < 4; ks++) {
            af[ks][0] = *(const uint32_t*)&q1[16 * ks + 2 * lr];
            af[ks][1] = *(const uint32_t*)&q2[16 * ks + 2 * lr];
            af[ks][2] = *(const uint32_t*)&q1[16 * ks + 8 + 2 * lr];
            af[ks][3] = *(const uint32_t*)&q2[16 * ks + 8 + 2 * lr];
        }

        int base1 = (13 - r1c / 14) * 27 + (13 - r1c % 14);
        int base2 = (13 - r2c / 14) * 27 + (13 - r2c % 14);

        float ao[8][4];
#pragma unroll
        for (int nt = 0; nt < 8; nt++)
#pragma unroll
            for (int t = 0; t < 4; t++) ao[nt][t] = 0.f;
        float sum1 = 0.f, sum2 = 0.f;

#pragma unroll
        for (int ch = 0; ch < 2; ch++) {
            float acc[CNT][4];
#pragma unroll
            for (int nt = 0; nt < CNT; nt++)
#pragma unroll
                for (int t = 0; t < 4; t++) acc[nt][t] = 0.f;

#pragma unroll
            for (int ks = 0; ks < 4; ks++) {
#pragma unroll
                for (int np = 0; np < 7; np++) {
                    uint32_t bf[2][2];
                    LDSM_X4(bf[0][0], bf[0][1], bf[1][0], bf[1][1],
                            kAddrBase + ((ch * CNT + 2 * np) * 8 * KSH_W + 8 * ks) * 4);
                    mma_f16(acc[2 * np], af[ks], bf[0][0], bf[0][1]);
                    mma_f16(acc[2 * np + 1], af[ks], bf[1][0], bf[1][1]);
                }
            }

#pragma unroll
            for (int nt = 0; nt < CNT; nt++) {
#pragma unroll
                for (int t = 0; t < 2; t++) {
                    int c = ch * 112 + nt * 8 + lr * 2 + t;
                    int code = colc[c];
                    float p1 = posh[code + base1];
                    float p2 = posh[code + base2];
                    float e1 = __expf(acc[nt][t] * SCALE * p1);
                    float e2 = __expf(acc[nt][2 + t] * SCALE * p2);
                    if (c > 195) { e1 = 0.f; e2 = 0.f; }
                    acc[nt][t] = e1;
                    acc[nt][2 + t] = e2;
                    sum1 += e1;
                    sum2 += e2;
                }
            }

            // PV: B-fragments via ldmatrix.trans on untransposed V
#pragma unroll
            for (int ks = 0; ks < 7; ks++) {
                int j0 = 16 * (ch * 7 + ks);
                uint32_t pa[4];
                pa[0] = packh2(acc[2 * ks][0], acc[2 * ks][1]);
                pa[1] = packh2(acc[2 * ks][2], acc[2 * ks][3]);
                pa[2] = packh2(acc[2 * ks + 1][0], acc[2 * ks + 1][1]);
                pa[3] = packh2(acc[2 * ks + 1][2], acc[2 * ks + 1][3]);
#pragma unroll
                for (int np = 0; np < 4; np++) {
                    uint32_t bf[2][2];
                    LDSM_X4_T(bf[0][0], bf[0][1], bf[1][0], bf[1][1],
                              vAddrBase + j0 * VSH_W * 4 + np * 32);
                    mma_f16(ao[2 * np], pa, bf[0][0], bf[0][1]);
                    mma_f16(ao[2 * np + 1], pa, bf[1][0], bf[1][1]);
                }
            }
        }

        sum1 += __shfl_xor_sync(0xffffffffu, sum1, 1);
        sum1 += __shfl_xor_sync(0xffffffffu, sum1, 2);
        sum2 += __shfl_xor_sync(0xffffffffu, sum2, 1);
        sum2 += __shfl_xor_sync(0xffffffffu, sum2, 2);
        float inv1 = 1.f / sum1;
        float inv2 = 1.f / sum2;

#pragma unroll
        for (int nt = 0; nt < 8; nt++) {
            int c = nt * 8 + lr * 2;
            if (r1 < SEQ)
                *(uint32_t*)&og[(size_t)(b * SEQ + r1) * DIM + h * HEAD_DIM + c] =
                    packh2(ao[nt][0] * inv1, ao[nt][1] * inv1);
            if (r2 < SEQ)
                *(uint32_t*)&og[(size_t)(b * SEQ + r2) * DIM + h * HEAD_DIM + c] =
                    packh2(ao[nt][2] * inv2, ao[nt][3] * inv2);
        }
    }
}

// ---------------- launch ----------------
extern "C" void kernel_launch(void* const* d_in, const int* in_sizes, int n_in,
                              void* d_out, int out_size)
{
    const float* x      = (const float*)d_in[0];
    const float* qk_w   = (const float*)d_in[1];
    const float* v_w    = (const float*)d_in[2];
    const float* w1_w   = (const float*)d_in[3];
    const float* w1_b   = (const float*)d_in[4];
    const float* w2     = (const float*)d_in[5];
    const float* b2     = (const float*)d_in[6];
    const float* proj_w = (const float*)d_in[7];
    const float* proj_b = (const float*)d_in[8];
    float* out = (float*)d_out;

    __half *xh, *qkvh, *oh, *qkvwh, *pwh;
    float* pos_buf;
    cudaGetSymbolAddress((void**)&xh, gx_h);
    cudaGetSymbolAddress((void**)&qkvh, gqkv_h);
    cudaGetSymbolAddress((void**)&oh, go_h);
    cudaGetSymbolAddress((void**)&qkvwh, gqkvw_h);
    cudaGetSymbolAddress((void**)&pwh, gpw_h);
    cudaGetSymbolAddress((void**)&pos_buf, g_pos);

    cudaFuncSetAttribute(gemm_h<false>, cudaFuncAttributeMaxDynamicSharedMemorySize, HSM_BYTES);
    cudaFuncSetAttribute(gemm_h<true>, cudaFuncAttributeMaxDynamicSharedMemorySize, HSM_BYTES);

    // merged converts
    conv_all<<<(NCONV_TOT / 4 + 255) / 256, 256>>>(x, qk_w, v_w, proj_w, xh, qkvwh, pwh);
    pos_kernel<<<729, 384>>>(w1_w, w1_b, w2, b2, pos_buf);

    // fused qkv projection: (12544, 2304)
    {
        dim3 grid(QKVS / 128, MTOT / 256);
        gemm_h<false><<<grid, 256, HSM_BYTES>>>(xh, qkvwh, nullptr, qkvh, MTOT, QKVS, DIM);
    }
    // fused attention
    {
        int smem_bytes = ATTN_SM_WORDS * 4;
        cudaFuncSetAttribute(attn_mma, cudaFuncAttributeMaxDynamicSharedMemorySize, smem_bytes);
        attn_mma<<<BATCH * HEADS, 256, smem_bytes>>>(qkvh, pos_buf, oh);
    }
    // output projection (float out, with bias)
    {
        dim3 grid(DIM / 128, MTOT / 256);
        gemm_h<true><<<grid, 256, HSM_BYTES>>>(oh, pwh, proj_b, out, MTOT, DIM, DIM);
    }
}

// round 17
// speedup vs baseline: 1.0628x; 1.0628x over previous
#include <cuda_runtime.h>
#include <cuda_fp16.h>
#include <math.h>
#include <stdint.h>

#define DIM 768
#define HEADS 12
#define HEAD_DIM 64
#define BATCH 64
#define SEQ 196
#define MTOT (BATCH * SEQ)      // 12544
#define SCALE 0.125f
#define QKVS 2304               // combined q|k|v row stride

// ---------------- scratch (all fp16 intermediates) ----------------
__device__ __half gx_h[(size_t)MTOT * DIM];
__device__ __half gqkv_h[(size_t)MTOT * QKVS];     // q|k|v
__device__ __half go_h[(size_t)MTOT * DIM];
__device__ __half gqkvw_h[QKVS * DIM];             // qk_w rows 0..1535, v_w rows 1536..2303
__device__ __half gpw_h[DIM * DIM];
__device__ float g_pos[HEADS * 729];               // pre-scaled: pos * SCALE * log2(e)

// ---------------- helpers ----------------
__device__ __forceinline__ uint32_t packh2(float x, float y) {
    __half2 h = __floats2half2_rn(x, y);
    return *(uint32_t*)&h;
}

__device__ __forceinline__ float ex2(float x) {
    float r;
    asm("ex2.approx.f32 %0, %1;" : "=f"(r) : "f"(x));
    return r;
}

__device__ __forceinline__ void mma_f16(float* c, const uint32_t* a, uint32_t b0, uint32_t b1) {
    asm volatile(
        "mma.sync.aligned.m16n8k16.row.col.f32.f16.f16.f32 "
        "{%0,%1,%2,%3}, {%4,%5,%6,%7}, {%8,%9}, {%0,%1,%2,%3};\n"
        : "+f"(c[0]), "+f"(c[1]), "+f"(c[2]), "+f"(c[3])
        : "r"(a[0]), "r"(a[1]), "r"(a[2]), "r"(a[3]), "r"(b0), "r"(b1));
}

__device__ __forceinline__ uint32_t smem_u32(const void* p) {
    uint32_t a;
    asm("{ .reg .u64 t; cvta.to.shared.u64 t, %1; cvt.u32.u64 %0, t; }" : "=r"(a) : "l"(p));
    return a;
}

#define LDSM_X4(r0, r1, r2, r3, addr) \
    asm volatile("ldmatrix.sync.aligned.m8n8.x4.shared.b16 {%0,%1,%2,%3}, [%4];" \
                 : "=r"(r0), "=r"(r1), "=r"(r2), "=r"(r3) : "r"(addr))

#define LDSM_X4_T(r0, r1, r2, r3, addr) \
    asm volatile("ldmatrix.sync.aligned.m8n8.x4.trans.shared.b16 {%0,%1,%2,%3}, [%4];" \
                 : "=r"(r0), "=r"(r1), "=r"(r2), "=r"(r3) : "r"(addr))

#define CP_ASYNC16(smaddr, gptr) \
    asm volatile("cp.async.cg.shared.global [%0], [%1], 16;" :: "r"(smaddr), "l"(gptr) : "memory")
#define CP_COMMIT() asm volatile("cp.async.commit_group;" ::: "memory")
#define CP_WAIT(n)  asm volatile("cp.async.wait_group %0;" :: "n"(n) : "memory")

// ---------------- merged fp32 -> fp16 convert (x, qk_w, v_w, proj_w) ----------------
#define NX (MTOT * DIM)
#define NQK (2 * DIM * DIM)
#define NV (DIM * DIM)
#define NCONV_TOT (NX + NQK + NV + NV)

__global__ void conv_all(const float* __restrict__ x, const float* __restrict__ qk_w,
                         const float* __restrict__ v_w, const float* __restrict__ proj_w,
                         __half* __restrict__ xh, __half* __restrict__ qkvwh,
                         __half* __restrict__ pwh)
{
    size_t i = ((size_t)blockIdx.x * 256 + threadIdx.x) * 4;
    if (i >= NCONV_TOT) return;
    const float* src;
    __half* dst;
    size_t off;
    if (i < NX) { src = x; dst = xh; off = i; }
    else if (i < NX + NQK) { src = qk_w; dst = qkvwh; off = i - NX; }
    else if (i < NX + NQK + NV) { src = v_w; dst = qkvwh + NQK; off = i - NX - NQK; }
    else { src = proj_w; dst = pwh; off = i - NX - NQK - NV; }
    float4 v = *(const float4*)&src[off];
    uint2 p;
    p.x = packh2(v.x, v.y);
    p.y = packh2(v.z, v.w);
    *(uint2*)&dst[off] = p;
}

// ---------------- pos table (pre-scaled by SCALE * log2(e)) ----------------
__global__ void pos_kernel(const float* __restrict__ w1,
                           const float* __restrict__ b1,
                           const float* __restrict__ w2,
                           const float* __restrict__ b2,
                           float* __restrict__ out)
{
    int c = blockIdx.x;
    float dx = (float)(c % 27 - 13);
    float dy = (float)(c / 27 - 13);
    int h = threadIdx.x >> 5;
    int lane = threadIdx.x & 31;
    float sum = 0.f;
#pragma unroll
    for (int mm = lane; mm < HEAD_DIM; mm += 32) {
        int g = h * HEAD_DIM + mm;
        float t = fmaf(dx, w1[g * 2 + 0], fmaf(dy, w1[g * 2 + 1], b1[g]));
        t = fmaxf(t, 0.f);
        sum += t * w2[g];
    }
#pragma unroll
    for (int o = 16; o > 0; o >>= 1) sum += __shfl_xor_sync(0xffffffffu, sum, o);
    if (lane == 0)
        out[h * 729 + c] = (sum + b2[h]) * (SCALE * 1.44269504088896f);
}

// ---------------- pure-fp16 GEMM (R14 geometry): 128x128, 3-stage, 2 CTA/SM ----
#define HSTRW 36
#define HBUF_W (2 * 128 * HSTRW)        // words per stage (A then B)
#define HSM_BYTES (3 * HBUF_W * 4)      // 110592

template <bool OUT_FLOAT>
__global__ __launch_bounds__(256, 2)
void gemm_h(const __half* __restrict__ A, const __half* __restrict__ B,
            const float* __restrict__ bias, void* __restrict__ Cout,
            int M, int N, int K)
{
    extern __shared__ uint32_t sm[];

    int tid = threadIdx.x;
    int lane = tid & 31;
    int w = tid >> 5;
    int wm = w >> 2;            // 0..1
    int wn = w & 3;             // 0..3
    int lq = lane >> 2;         // 0..7
    int lr = lane & 3;          // 0..3
    int m0 = blockIdx.y * 128;
    int n0 = blockIdx.x * 128;

    uint32_t rowSelA = (lane & 7) + ((lane >> 3) & 1) * 8;
    uint32_t colSelA = (lane >> 4) * 4;
    uint32_t rowSelB = (lane & 7) + (lane >> 4) * 8;
    uint32_t colSelB = ((lane >> 3) & 1) * 4;

    float acc[4][4][4];
#pragma unroll
    for (int i = 0; i < 4; i++)
#pragma unroll
        for (int j = 0; j < 4; j++)
#pragma unroll
            for (int t = 0; t < 4; t++) acc[i][j][t] = 0.f;

    uint32_t smb = smem_u32(sm);
    int NT_K = K / 64;

    auto issue = [&](int buf, int k0) {
#pragma unroll
        for (int i = 0; i < 4; i++) {
            int c = tid + i * 256;
            int row = c >> 3, c8 = c & 7;
            uint32_t dstA = smb + (buf * HBUF_W + row * HSTRW + c8 * 4) * 4;
            CP_ASYNC16(dstA, A + (size_t)(m0 + row) * K + k0 + c8 * 8);
            uint32_t dstB = smb + (buf * HBUF_W + (128 + row) * HSTRW + c8 * 4) * 4;
            CP_ASYNC16(dstB, B + (size_t)(n0 + row) * K + k0 + c8 * 8);
        }
        CP_COMMIT();
    };

    issue(0, 0);
    issue(1, 64);

    int buf = 0;
    for (int kt = 0; kt < NT_K; kt++) {
        CP_WAIT(1);
        __syncthreads();

        if (kt + 2 < NT_K) issue((kt + 2) % 3, (kt + 2) * 64);
        else CP_COMMIT();           // keep wait(1) invariant at tail

        uint32_t abase = smb + (buf * HBUF_W) * 4;
        uint32_t aAddr = abase + ((wm * 64 + rowSelA) * HSTRW + colSelA) * 4;
        uint32_t bAddr = abase + ((128 + wn * 32 + rowSelB) * HSTRW + colSelB) * 4;

#pragma unroll
        for (int ks = 0; ks < 4; ks++) {
            int kb = ks * 8;
            uint32_t af[4][4], bf[4][2];
#pragma unroll
            for (int i = 0; i < 4; i++)
                LDSM_X4(af[i][0], af[i][1], af[i][2], af[i][3],
                        aAddr + (i * 16 * HSTRW + kb) * 4);
#pragma unroll
            for (int jp = 0; jp < 2; jp++)
                LDSM_X4(bf[2 * jp][0], bf[2 * jp][1], bf[2 * jp + 1][0], bf[2 * jp + 1][1],
                        bAddr + (jp * 16 * HSTRW + kb) * 4);
#pragma unroll
            for (int i = 0; i < 4; i++)
#pragma unroll
                for (int j = 0; j < 4; j++)
                    mma_f16(acc[i][j], af[i], bf[j][0], bf[j][1]);
        }
        buf = (buf + 1) % 3;
    }

#pragma unroll
    for (int i = 0; i < 4; i++) {
#pragma unroll
        for (int j = 0; j < 4; j++) {
            int row = m0 + wm * 64 + i * 16 + lq;
            int col = n0 + wn * 32 + j * 8 + lr * 2;
            float b0 = bias ? bias[col] : 0.f;
            float b1 = bias ? bias[col + 1] : 0.f;
            if (OUT_FLOAT) {
                float* C = (float*)Cout;
                *(float2*)&C[(size_t)row * N + col] =
                    make_float2(acc[i][j][0] + b0, acc[i][j][1] + b1);
                *(float2*)&C[(size_t)(row + 8) * N + col] =
                    make_float2(acc[i][j][2] + b0, acc[i][j][3] + b1);
            } else {
                __half* C = (__half*)Cout;
                *(uint32_t*)&C[(size_t)row * N + col] = packh2(acc[i][j][0] + b0, acc[i][j][1] + b1);
                *(uint32_t*)&C[(size_t)(row + 8) * N + col] = packh2(acc[i][j][2] + b0, acc[i][j][3] + b1);
            }
        }
    }
}

// ---------------- FP16 MMA attention: cp.async staging + ex2 softmax ----------
// smem: K [224][72 halves], V [224][72 halves] (rows j, cols d), pos[729], colc[224]
#define KSH_W 36            // words per K row
#define VSH_W 36            // words per V row
#define NPAD 224
#define CNT 14
#define ATTN_SM_WORDS (NPAD * KSH_W + NPAD * VSH_W + 729 + NPAD)

__global__ __launch_bounds__(256, 2)
void attn_mma(const __half* __restrict__ qkv,
              const float* __restrict__ pos,
              __half* __restrict__ og)
{
    extern __shared__ uint32_t smu[];
    uint32_t* Kw   = smu;                        // [224][36] words
    uint32_t* Vw   = Kw + NPAD * KSH_W;          // [224][36] words (V rows j)
    float*    posh = (float*)(Vw + NPAD * VSH_W);
    int*      colc = (int*)(posh + 729);

    int bh = blockIdx.x;
    int b = bh / HEADS;
    int h = bh % HEADS;
    int tid = threadIdx.x;
    int w = tid >> 5;
    int lane = tid & 31;
    int lq = lane >> 2;
    int lr = lane & 3;

    // K (non-trans) selectors
    uint32_t rowSelB = (lane & 7) + (lane >> 4) * 8;
    uint32_t colSelB = ((lane >> 3) & 1) * 4;
    // V (trans) selectors
    uint32_t rowSelV = (lane & 7) + ((lane >> 3) & 1) * 8;
    uint32_t colSelV = (lane >> 4) * 8;
    uint32_t kAddrBase, vAddrBase, kSmBase, vSmBase;
    {
        kSmBase = smem_u32(Kw);
        vSmBase = smem_u32(Vw);
        kAddrBase = kSmBase + (rowSelB * KSH_W + colSelB) * 4;
        vAddrBase = vSmBase + rowSelV * VSH_W * 4 + colSelV * 2;
    }

    // zero pads: K and V rows 196..223
    for (int idx = tid; idx < 28 * KSH_W; idx += 256) {
        Kw[196 * KSH_W + idx] = 0;
        Vw[196 * VSH_W + idx] = 0;
    }

    // stage K and V rows 0..195 via cp.async
    for (int idx = tid; idx < SEQ * 8; idx += 256) {
        int j = idx >> 3, c8 = idx & 7;
        CP_ASYNC16(kSmBase + (j * KSH_W + c8 * 4) * 4,
                   &qkv[(size_t)(b * SEQ + j) * QKVS + DIM + h * HEAD_DIM + c8 * 8]);
        CP_ASYNC16(vSmBase + (j * VSH_W + c8 * 4) * 4,
                   &qkv[(size_t)(b * SEQ + j) * QKVS + 2 * DIM + h * HEAD_DIM + c8 * 8]);
    }
    CP_COMMIT();
    for (int c = tid; c < 729; c += 256) posh[c] = pos[h * 729 + c];
    for (int c = tid; c < NPAD; c += 256) {
        int cc = c > 195 ? 195 : c;
        colc[c] = (cc / 14) * 27 + (cc % 14);
    }
    CP_WAIT(0);
    __syncthreads();

    for (int mt = w; mt < 13; mt += 8) {
        int m0 = mt * 16;
        int r1 = m0 + lq, r2 = r1 + 8;
        int r1c = r1 > 195 ? 195 : r1;
        int r2c = r2 > 195 ? 195 : r2;
        const __half* q1 = &qkv[(size_t)(b * SEQ + r1c) * QKVS + h * HEAD_DIM];
        const __half* q2 = &qkv[(size_t)(b * SEQ + r2c) * QKVS + h * HEAD_DIM];

        uint32_t af[4][4];
#pragma unroll
        for (int ks = 0; ks < 4; ks++) {
            af[ks][0] = *(const uint32_t*)&q1[16 * ks + 2 * lr];
            af[ks][1] = *(const uint32_t*)&q2[16 * ks + 2 * lr];
            af[ks][2] = *(const uint32_t*)&q1[16 * ks + 8 + 2 * lr];
            af[ks][3] = *(const uint32_t*)&q2[16 * ks + 8 + 2 * lr];
        }

        int base1 = (13 - r1c / 14) * 27 + (13 - r1c % 14);
        int base2 = (13 - r2c / 14) * 27 + (13 - r2c % 14);

        float ao[8][4];
#pragma unroll
        for (int nt = 0; nt < 8; nt++)
#pragma unroll
            for (int t = 0; t < 4; t++) ao[nt][t] = 0.f;
        float s1a = 0.f, s1b = 0.f, s2a = 0.f, s2b = 0.f;

#pragma unroll
        for (int ch = 0; ch < 2; ch++) {
            float acc[CNT][4];
#pragma unroll
            for (int nt = 0; nt < CNT; nt++)
#pragma unroll
                for (int t = 0; t < 4; t++) acc[nt][t] = 0.f;

#pragma unroll
            for (int ks = 0; ks < 4; ks++) {
#pragma unroll
                for (int np = 0; np < 7; np++) {
                    uint32_t bf[2][2];
                    LDSM_X4(bf[0][0], bf[0][1], bf[1][0], bf[1][1],
                            kAddrBase + ((ch * CNT + 2 * np) * 8 * KSH_W + 8 * ks) * 4);
                    mma_f16(acc[2 * np], af[ks], bf[0][0], bf[0][1]);
                    mma_f16(acc[2 * np + 1], af[ks], bf[1][0], bf[1][1]);
                }
            }

            // exp2(acc * posh) — posh pre-scaled by SCALE*log2e
#pragma unroll
            for (int nt = 0; nt < CNT; nt++) {
                int c0 = ch * 112 + nt * 8 + lr * 2;
                int code0 = colc[c0], code1 = colc[c0 + 1];
                float p10 = posh[code0 + base1], p11 = posh[code1 + base1];
                float p20 = posh[code0 + base2], p21 = posh[code1 + base2];
                float e10 = ex2(acc[nt][0] * p10);
                float e11 = ex2(acc[nt][1] * p11);
                float e20 = ex2(acc[nt][2] * p20);
                float e21 = ex2(acc[nt][3] * p21);
                if (c0 > 195)     { e10 = 0.f; e20 = 0.f; }
                if (c0 + 1 > 195) { e11 = 0.f; e21 = 0.f; }
                acc[nt][0] = e10; acc[nt][1] = e11;
                acc[nt][2] = e20; acc[nt][3] = e21;
                s1a += e10; s1b += e11;
                s2a += e20; s2b += e21;
            }

            // PV: B-fragments via ldmatrix.trans on untransposed V
#pragma unroll
            for (int ks = 0; ks < 7; ks++) {
                int j0 = 16 * (ch * 7 + ks);
                uint32_t pa[4];
                pa[0] = packh2(acc[2 * ks][0], acc[2 * ks][1]);
                pa[1] = packh2(acc[2 * ks][2], acc[2 * ks][3]);
                pa[2] = packh2(acc[2 * ks + 1][0], acc[2 * ks + 1][1]);
                pa[3] = packh2(acc[2 * ks + 1][2], acc[2 * ks + 1][3]);
#pragma unroll
                for (int np = 0; np < 4; np++) {
                    uint32_t bf[2][2];
                    LDSM_X4_T(bf[0][0], bf[0][1], bf[1][0], bf[1][1],
                              vAddrBase + j0 * VSH_W * 4 + np * 32);
                    mma_f16(ao[2 * np], pa, bf[0][0], bf[0][1]);
                    mma_f16(ao[2 * np + 1], pa, bf[1][0], bf[1][1]);
                }
            }
        }

        float sum1 = s1a + s1b;
        float sum2 = s2a + s2b;
        sum1 += __shfl_xor_sync(0xffffffffu, sum1, 1);
        sum1 += __shfl_xor_sync(0xffffffffu, sum1, 2);
        sum2 += __shfl_xor_sync(0xffffffffu, sum2, 1);
        sum2 += __shfl_xor_sync(0xffffffffu, sum2, 2);
        float inv1 = 1.f / sum1;
        float inv2 = 1.f / sum2;

#pragma unroll
        for (int nt = 0; nt < 8; nt++) {
            int c = nt * 8 + lr * 2;
            if (r1 < SEQ)
                *(uint32_t*)&og[(size_t)(b * SEQ + r1) * DIM + h * HEAD_DIM + c] =
                    packh2(ao[nt][0] * inv1, ao[nt][1] * inv1);
            if (r2 < SEQ)
                *(uint32_t*)&og[(size_t)(b * SEQ + r2) * DIM + h * HEAD_DIM + c] =
                    packh2(ao[nt][2] * inv2, ao[nt][3] * inv2);
        }
    }
}

// ---------------- launch ----------------
extern "C" void kernel_launch(void* const* d_in, const int* in_sizes, int n_in,
                              void* d_out, int out_size)
{
    const float* x      = (const float*)d_in[0];
    const float* qk_w   = (const float*)d_in[1];
    const float* v_w    = (const float*)d_in[2];
    const float* w1_w   = (const float*)d_in[3];
    const float* w1_b   = (const float*)d_in[4];
    const float* w2     = (const float*)d_in[5];
    const float* b2     = (const float*)d_in[6];
    const float* proj_w = (const float*)d_in[7];
    const float* proj_b = (const float*)d_in[8];
    float* out = (float*)d_out;

    __half *xh, *qkvh, *oh, *qkvwh, *pwh;
    float* pos_buf;
    cudaGetSymbolAddress((void**)&xh, gx_h);
    cudaGetSymbolAddress((void**)&qkvh, gqkv_h);
    cudaGetSymbolAddress((void**)&oh, go_h);
    cudaGetSymbolAddress((void**)&qkvwh, gqkvw_h);
    cudaGetSymbolAddress((void**)&pwh, gpw_h);
    cudaGetSymbolAddress((void**)&pos_buf, g_pos);

    cudaFuncSetAttribute(gemm_h<false>, cudaFuncAttributeMaxDynamicSharedMemorySize, HSM_BYTES);
    cudaFuncSetAttribute(gemm_h<true>, cudaFuncAttributeMaxDynamicSharedMemorySize, HSM_BYTES);

    // merged converts
    conv_all<<<(NCONV_TOT / 4 + 255) / 256, 256>>>(x, qk_w, v_w, proj_w, xh, qkvwh, pwh);
    pos_kernel<<<729, 384>>>(w1_w, w1_b, w2, b2, pos_buf);

    // fused qkv projection: (12544, 2304)
    {
        dim3 grid(QKVS / 128, MTOT / 128);
        gemm_h<false><<<grid, 256, HSM_BYTES>>>(xh, qkvwh, nullptr, qkvh, MTOT, QKVS, DIM);
    }
    // fused attention
    {
        int smem_bytes = ATTN_SM_WORDS * 4;
        cudaFuncSetAttribute(attn_mma, cudaFuncAttributeMaxDynamicSharedMemorySize, smem_bytes);
        attn_mma<<<BATCH * HEADS, 256, smem_bytes>>>(qkvh, pos_buf, oh);
    }
    // output projection (float out, with bias)
    {
        dim3 grid(DIM / 128, MTOT / 128);
        gemm_h<true><<<grid, 256, HSM_BYTES>>>(oh, pwh, proj_b, out, MTOT, DIM, DIM);
    }
}